// round 15
// baseline (speedup 1.0000x reference)
#include <cuda_runtime.h>
#include <cuda_fp16.h>

// Problem constants (shapes fixed by setup_inputs): B=2, H=W=256, D=128, C=4.
constexpr int   DVOX    = 128;
constexpr int   HPIX    = 256;
constexpr int   WPIX    = 256;
constexpr int   BBATCH  = 2;
constexpr float DT      = 0.03125f;            // 2^-5, EXACT power of two
constexpr int   NSTEPS  = 111;                 // ceil(2*sqrt(3)/DT) = 37 * 3
constexpr int   VOXELS  = DVOX * DVOX * DVOX;  // 2097152 per batch per channel

// 64 MB scratch: volume as fp16, x-pair duplicated:
// g_vol[b][z][y][x] = { c0..c3 @ x , c0..c3 @ x+1 }  (8 halves = 16 B, aligned)
// One LDG.128 fetches a full x-corner pair for all 4 channels.
__device__ uint4 g_vol[(size_t)BBATCH * VOXELS];

// ---------------------------------------------------------------------------
// Pass 1: fp16 convert + channel interleave + x-pair duplication.
// Moves 192 MB total -> already at HBM roofline (~23 us), compulsory traffic.
// ---------------------------------------------------------------------------
__global__ void __launch_bounds__(128)
interleave_kernel(const float* __restrict__ vol)
{
    __shared__ unsigned int s01[DVOX];   // half2(c0,c1) per x
    __shared__ unsigned int s23[DVOX];   // half2(c2,c3) per x

    int x   = threadIdx.x;
    int row = blockIdx.x;                        // flat over B * 128 * 128 rows
    int b   = row >> 14;                         // / (128*128)
    int zy  = row & (DVOX * DVOX - 1);

    const float* p = vol + (size_t)b * 4 * VOXELS + (size_t)zy * DVOX + x;
    __half2 a01 = __halves2half2(__float2half_rn(p[0]),
                                 __float2half_rn(p[VOXELS]));
    __half2 a23 = __halves2half2(__float2half_rn(p[2 * VOXELS]),
                                 __float2half_rn(p[3 * VOXELS]));
    s01[x] = *reinterpret_cast<unsigned int*>(&a01);
    s23[x] = *reinterpret_cast<unsigned int*>(&a23);
    __syncthreads();

    int x1 = (x < DVOX - 1) ? x + 1 : x;         // x=127 slot is never sampled
    uint4 u;
    u.x = s01[x];  u.y = s23[x];
    u.z = s01[x1]; u.w = s23[x1];
    g_vol[(size_t)b * VOXELS + (size_t)zy * DVOX + x] = u;
}

// ---------------------------------------------------------------------------
// half2 helpers
// ---------------------------------------------------------------------------
__device__ __forceinline__ __half2 H2(unsigned int u)
{
    return *reinterpret_cast<__half2*>(&u);
}
__device__ __forceinline__ __half2 h2lerp(__half2 a, __half2 b, __half2 t)
{
    return __hfma2(__hsub2(b, a), t, a);   // a + t*(b-a)
}

// Full-half2 trilinear sample: 4 corner-row regs (each holds {c@x, c@x+1} for
// 4 channels), fp16 frac weights, single fp32 conversion at the end.
__device__ __forceinline__ float4 trilerp(uint4 r00, uint4 r01,
                                          uint4 r10, uint4 r11,
                                          float ffx, float ffy, float ffz)
{
    __half2 fx = __float2half2_rn(ffx);
    __half2 fy = __float2half2_rn(ffy);
    __half2 fz = __float2half2_rn(ffz);

    __half2 x00a = h2lerp(H2(r00.x), H2(r00.z), fx);  // ch 0,1
    __half2 x00b = h2lerp(H2(r00.y), H2(r00.w), fx);  // ch 2,3
    __half2 x01a = h2lerp(H2(r01.x), H2(r01.z), fx);
    __half2 x01b = h2lerp(H2(r01.y), H2(r01.w), fx);
    __half2 x10a = h2lerp(H2(r10.x), H2(r10.z), fx);
    __half2 x10b = h2lerp(H2(r10.y), H2(r10.w), fx);
    __half2 x11a = h2lerp(H2(r11.x), H2(r11.z), fx);
    __half2 x11b = h2lerp(H2(r11.y), H2(r11.w), fx);

    __half2 y0a = h2lerp(x00a, x01a, fy);
    __half2 y0b = h2lerp(x00b, x01b, fy);
    __half2 y1a = h2lerp(x10a, x11a, fy);
    __half2 y1b = h2lerp(x10b, x11b, fy);

    __half2 za = h2lerp(y0a, y1a, fz);
    __half2 zb = h2lerp(y0b, y1b, fz);

    float2 f01 = __half22float2(za);
    float2 f23 = __half22float2(zb);
    return make_float4(f01.x, f01.y, f23.x, f23.y);
}

// Grid coord + cell index + frac. g = fma(pos, 63.5, 63.5) — continuous vs the
// reference's op chain (trilinear is continuous across cell flips), only the
// validity test (done on exact pos) is discrete. Integer clamp keeps the
// address in-bounds for gated-off (invalid) samples.
__device__ __forceinline__ void coord(float pos, int& i0, float& fr)
{
    float g = __fmaf_rn(pos, 63.5f, 63.5f);
    int i = (int)g;                 // trunc; g<0 only when invalid (gated off)
    i0 = min(max(i, 0), 126);
    fr = g - (float)i0;
}

// ---------------------------------------------------------------------------
// Pass 2: ray march. Thread->pixel remap gives each WARP an 8x4 pixel patch
// (footprint ~2x1 voxels instead of a 32x1 strip's ~8 voxels): the warp's
// corner loads collapse onto 1-2 cache lines each -> far fewer L1 wavefronts
// and higher hit rate (the R7-measured binder was load-latency exposure).
// 3 steps per iteration (12 LDG.128 in flight; 111 = 37*3).
// Ray setup replicates XLA's un-contracted fp32 chain bit-exactly (first
// sample sits ON the z=-1 face; validity there is a 1-ulp knife edge).
// ---------------------------------------------------------------------------
__global__ void __launch_bounds__(128)
raymarch_kernel(const float* __restrict__ camrot,
                const float* __restrict__ campos,
                const float* __restrict__ focal,
                const float* __restrict__ princpt,
                const float* __restrict__ pixelcoords,
                float* __restrict__ out)
{
    // Block = 16x8 pixel tile; warp = 8x4 patch.
    // lane: lx = lane&7, ly = lane>>3 (0..3)
    // warp w (0..3): x-half = w&1, y-half = w>>1
    int tid  = threadIdx.x;
    int lane = tid & 31;
    int warp = tid >> 5;
    int lx = lane & 7, ly = lane >> 3;

    int tilesX = WPIX / 16;                       // 16 tiles per row
    int tileId = blockIdx.x;                      // [0, B*16*32)
    int b      = tileId >= (tilesX * (HPIX / 8)) ? 1 : 0;
    int t      = tileId - b * (tilesX * (HPIX / 8));
    int tileY  = t / tilesX;
    int tileX  = t - tileY * tilesX;

    int w = tileX * 16 + (warp & 1) * 8 + lx;
    int h = tileY * 8  + (warp >> 1) * 4 + ly;
    int idx = (b << 16) + (h << 8) + w;           // flat pixel index

    float2 pc = reinterpret_cast<const float2*>(pixelcoords)[idx];

    float fx = focal[b * 2 + 0], fy = focal[b * 2 + 1];
    float px = princpt[b * 2 + 0], py = princpt[b * 2 + 1];

    // (pixel - princpt) / focal : rn sub, rn div (XLA: separate ops, no FMA)
    float rx = __fdiv_rn(__fsub_rn(pc.x, px), fx);
    float ry = __fdiv_rn(__fsub_rn(pc.y, py), fy);
    float rz = 1.0f;

    const float* R = camrot + b * 9;   // camrot^T applied
    float dx = __fadd_rn(__fadd_rn(__fmul_rn(R[0], rx), __fmul_rn(R[3], ry)),
                         __fmul_rn(R[6], rz));
    float dy = __fadd_rn(__fadd_rn(__fmul_rn(R[1], rx), __fmul_rn(R[4], ry)),
                         __fmul_rn(R[7], rz));
    float dz = __fadd_rn(__fadd_rn(__fmul_rn(R[2], rx), __fmul_rn(R[5], ry)),
                         __fmul_rn(R[8], rz));

    float s = __fadd_rn(__fadd_rn(__fmul_rn(dx, dx), __fmul_rn(dy, dy)),
                        __fmul_rn(dz, dz));
    float nrm = sqrtf(s);
    dx = __fdiv_rn(dx, nrm);
    dy = __fdiv_rn(dy, nrm);
    dz = __fdiv_rn(dz, nrm);

    float cx = campos[b * 3 + 0], cy = campos[b * 3 + 1], cz = campos[b * 3 + 2];

    float t1x = __fdiv_rn(__fsub_rn(-1.0f, cx), dx);
    float t2x = __fdiv_rn(__fsub_rn( 1.0f, cx), dx);
    float t1y = __fdiv_rn(__fsub_rn(-1.0f, cy), dy);
    float t2y = __fdiv_rn(__fsub_rn( 1.0f, cy), dy);
    float t1z = __fdiv_rn(__fsub_rn(-1.0f, cz), dz);
    float t2z = __fdiv_rn(__fsub_rn( 1.0f, cz), dz);
    float tmin = fmaxf(fminf(t1x, t2x),
                 fmaxf(fminf(t1y, t2y), fminf(t1z, t2z)));
    float tmax = fminf(fmaxf(t1x, t2x),
                 fminf(fmaxf(t1y, t2y), fmaxf(t1z, t2z)));
    bool hit = tmin < tmax;
    float t0 = fmaxf(hit ? tmin : 0.0f, 0.0f);

    // pos = campos + raydir*t0 : separate rn mul + rn add (knife edge)
    float posx = __fadd_rn(cx, __fmul_rn(dx, t0));
    float posy = __fadd_rn(cy, __fmul_rn(dy, t0));
    float posz = __fadd_rn(cz, __fmul_rn(dz, t0));

    // DT = 2^-5 => dir*DT is exact; per-step pos update is one rn add.
    float sx = dx * DT, sy = dy * DT, sz = dz * DT;

    float accR = 0.0f, accG = 0.0f, accB = 0.0f, accA = 0.0f;

    if (hit) {
        const uint4* __restrict__ volb = g_vol + (size_t)b * VOXELS;
        bool wasValid = false;

        #pragma unroll 1
        for (int it = 0; it < NSTEPS / 3; ++it) {        // 37 triples = 111
            // Sequential rn position chain (bit-identical to reference).
            float pbx = posx + sx, pby = posy + sy, pbz = posz + sz;
            float pcx = pbx + sx,  pcy = pby + sy,  pcz = pbz + sz;

            bool validA = (posx > -1.0f) & (posx < 1.0f) &
                          (posy > -1.0f) & (posy < 1.0f) &
                          (posz > -1.0f) & (posz < 1.0f);
            // Convex cube: once inside then outside, never inside again.
            if (wasValid & !validA) break;
            bool validB = (pbx > -1.0f) & (pbx < 1.0f) &
                          (pby > -1.0f) & (pby < 1.0f) &
                          (pbz > -1.0f) & (pbz < 1.0f);
            bool validC = (pcx > -1.0f) & (pcx < 1.0f) &
                          (pcy > -1.0f) & (pcy < 1.0f) &
                          (pcz > -1.0f) & (pcz < 1.0f);

            int xa, ya, za2, xb, yb, zb2, xc, yc, zc2;
            float fxa, fya, fza, fxb, fyb, fzb, fxc, fyc, fzc;
            coord(posx, xa, fxa); coord(posy, ya, fya); coord(posz, za2, fza);
            coord(pbx, xb, fxb);  coord(pby, yb, fyb);  coord(pbz, zb2, fzb);
            coord(pcx, xc, fxc);  coord(pcy, yc, fyc);  coord(pcz, zc2, fzc);

            int baseA = (((za2 << 7) + ya) << 7) + xa;
            int baseB = (((zb2 << 7) + yb) << 7) + xb;
            int baseC = (((zc2 << 7) + yc) << 7) + xc;

            // --- 12 loads for all three steps, issued together ---
            uint4 a00 = __ldg(volb + baseA);
            uint4 a01 = __ldg(volb + baseA + DVOX);
            uint4 a10 = __ldg(volb + baseA + DVOX * DVOX);
            uint4 a11 = __ldg(volb + baseA + DVOX * DVOX + DVOX);
            uint4 b00 = __ldg(volb + baseB);
            uint4 b01 = __ldg(volb + baseB + DVOX);
            uint4 b10 = __ldg(volb + baseB + DVOX * DVOX);
            uint4 b11 = __ldg(volb + baseB + DVOX * DVOX + DVOX);
            uint4 c00 = __ldg(volb + baseC);
            uint4 c01 = __ldg(volb + baseC + DVOX);
            uint4 c10 = __ldg(volb + baseC + DVOX * DVOX);
            uint4 c11 = __ldg(volb + baseC + DVOX * DVOX + DVOX);

            {
                float4 smp = trilerp(a00, a01, a10, a11, fxa, fya, fza);
                float va = validA ? 1.0f : 0.0f;
                float contrib = (fminf(accA + smp.w * DT, 1.0f) - accA) * va;
                accR += smp.x * contrib;
                accG += smp.y * contrib;
                accB += smp.z * contrib;
                accA += contrib;
            }
            {
                float4 smp = trilerp(b00, b01, b10, b11, fxb, fyb, fzb);
                float vb = validB ? 1.0f : 0.0f;
                float contrib = (fminf(accA + smp.w * DT, 1.0f) - accA) * vb;
                accR += smp.x * contrib;
                accG += smp.y * contrib;
                accB += smp.z * contrib;
                accA += contrib;
            }
            {
                float4 smp = trilerp(c00, c01, c10, c11, fxc, fyc, fzc);
                float vc = validC ? 1.0f : 0.0f;
                float contrib = (fminf(accA + smp.w * DT, 1.0f) - accA) * vc;
                accR += smp.x * contrib;
                accG += smp.y * contrib;
                accB += smp.z * contrib;
                accA += contrib;
            }

            // volume >= 0: alpha saturates to exactly 1.0, contrib 0 forever.
            if (accA >= 1.0f) break;
            wasValid |= (validA | validB | validC);

            posx = pcx + sx;
            posy = pcy + sy;
            posz = pcz + sz;
        }
    }

    // out: [B,4,H,W]
    int o = ((b * 4) * HPIX + h) * WPIX + w;
    const int CS = HPIX * WPIX;
    out[o]          = accR;
    out[o + CS]     = accG;
    out[o + 2 * CS] = accB;
    out[o + 3 * CS] = accA;
}

extern "C" void kernel_launch(void* const* d_in, const int* in_sizes, int n_in,
                              void* d_out, int out_size)
{
    const float* camrot      = (const float*)d_in[0];
    const float* campos      = (const float*)d_in[1];
    const float* focal       = (const float*)d_in[2];
    const float* princpt     = (const float*)d_in[3];
    const float* pixelcoords = (const float*)d_in[4];
    const float* volume      = (const float*)d_in[5];
    float* out = (float*)d_out;

    int B = in_sizes[1] / 3;                       // = 2
    int nrows = B * DVOX * DVOX;                   // one block per x-row
    interleave_kernel<<<nrows, DVOX>>>(volume);

    int npix = B * HPIX * WPIX;                    // 131072
    raymarch_kernel<<<npix / 128, 128>>>(camrot, campos, focal, princpt,
                                         pixelcoords, out);
}

// round 16
// speedup vs baseline: 1.2009x; 1.2009x over previous
#include <cuda_runtime.h>
#include <cuda_fp16.h>

// Problem constants (shapes fixed by setup_inputs): B=2, H=W=256, D=128, C=4.
constexpr int   DVOX    = 128;
constexpr int   HPIX    = 256;
constexpr int   WPIX    = 256;
constexpr int   BBATCH  = 2;
constexpr float DT      = 0.03125f;            // 2^-5, EXACT power of two
constexpr int   NSTEPS  = 111;                 // ceil(2*sqrt(3)/DT)
constexpr int   VOXELS  = DVOX * DVOX * DVOX;  // 2097152 per batch per channel

// 64 MB scratch: volume as fp16, x-pair duplicated:
// g_vol[b][z][y][x] = { c0..c3 @ x , c0..c3 @ x+1 }  (8 halves = 16 B, aligned)
// One LDG.128 fetches a full x-corner pair for all 4 channels.
__device__ uint4 g_vol[(size_t)BBATCH * VOXELS];

// ---------------------------------------------------------------------------
// Pass 1: fp16 convert + channel interleave + x-pair duplication.
// Moves 192 MB total -> already at HBM roofline (~23 us), compulsory traffic.
// ---------------------------------------------------------------------------
__global__ void __launch_bounds__(128)
interleave_kernel(const float* __restrict__ vol)
{
    __shared__ unsigned int s01[DVOX];   // half2(c0,c1) per x
    __shared__ unsigned int s23[DVOX];   // half2(c2,c3) per x

    int x   = threadIdx.x;
    int row = blockIdx.x;                        // flat over B * 128 * 128 rows
    int b   = row >> 14;                         // / (128*128)
    int zy  = row & (DVOX * DVOX - 1);

    const float* p = vol + (size_t)b * 4 * VOXELS + (size_t)zy * DVOX + x;
    __half2 a01 = __halves2half2(__float2half_rn(p[0]),
                                 __float2half_rn(p[VOXELS]));
    __half2 a23 = __halves2half2(__float2half_rn(p[2 * VOXELS]),
                                 __float2half_rn(p[3 * VOXELS]));
    s01[x] = *reinterpret_cast<unsigned int*>(&a01);
    s23[x] = *reinterpret_cast<unsigned int*>(&a23);
    __syncthreads();

    int x1 = (x < DVOX - 1) ? x + 1 : x;         // x=127 slot is never sampled
    uint4 u;
    u.x = s01[x];  u.y = s23[x];
    u.z = s01[x1]; u.w = s23[x1];
    g_vol[(size_t)b * VOXELS + (size_t)zy * DVOX + x] = u;
}

// ---------------------------------------------------------------------------
// sampling helpers (R6-measured-best math: half2 x-lerp, fp32 y/z lerps)
// ---------------------------------------------------------------------------
__device__ __forceinline__ __half2 H2(unsigned int u)
{
    return *reinterpret_cast<__half2*>(&u);
}

// x-lerp one (z,y) corner row in half2, then convert to fp32 float4.
__device__ __forceinline__ float4 xlerp(uint4 r, __half2 omfx, __half2 fx)
{
    __half2 c01 = __hfma2(H2(r.z), fx, __hmul2(H2(r.x), omfx));
    __half2 c23 = __hfma2(H2(r.w), fx, __hmul2(H2(r.y), omfx));
    float2 f01 = __half22float2(c01);
    float2 f23 = __half22float2(c23);
    return make_float4(f01.x, f01.y, f23.x, f23.y);
}

__device__ __forceinline__ float4 lerp4(float4 a, float4 b, float t)
{
    float omt = 1.0f - t;
    return make_float4(a.x * omt + b.x * t,
                       a.y * omt + b.y * t,
                       a.z * omt + b.z * t,
                       a.w * omt + b.w * t);
}

// Grid coord + cell index + frac. g = fma(pos, 63.5, 63.5) — continuous vs the
// reference's op chain (trilinear is continuous across cell flips); only the
// validity test (done on exact pos) is discrete. Integer clamp keeps the
// address in-bounds even for gated-off (invalid) positions.
__device__ __forceinline__ void coord(float pos, int& i0, float& fr)
{
    float g = __fmaf_rn(pos, 63.5f, 63.5f);
    int i = (int)g;                 // trunc == floor for g >= 0
    i0 = min(max(i, 0), 126);
    fr = g - (float)i0;
}

// ---------------------------------------------------------------------------
// Pass 2: ray march, software-pipelined 1-step stages (ping-pong buffers):
// issue step n+1's 4 LDG.128, then do step n's math -> every load has a full
// step of independent work between issue and use, 8 loads in flight steady-
// state, and the load batch fits the register budget (grid-limited residency
// 27.7 warps/SM caps regs at ~74/thread; R7's 12-load batch broke this).
// Warp = 32x1 pixel strip (measured-best locality: one voxel row, ~2 lines
// per corner load). Ray setup replicates XLA's un-contracted fp32 chain
// bit-exactly (first sample sits ON the z=-1 face; 1-ulp knife edge).
// ---------------------------------------------------------------------------
__global__ void __launch_bounds__(128, 7)
raymarch_kernel(const float* __restrict__ camrot,
                const float* __restrict__ campos,
                const float* __restrict__ focal,
                const float* __restrict__ princpt,
                const float* __restrict__ pixelcoords,
                float* __restrict__ out)
{
    int idx = blockIdx.x * blockDim.x + threadIdx.x;   // flat over B*H*W
    int w = idx & (WPIX - 1);
    int h = (idx >> 8) & (HPIX - 1);
    int b = idx >> 16;

    float2 pc = reinterpret_cast<const float2*>(pixelcoords)[idx];

    float fx = focal[b * 2 + 0], fy = focal[b * 2 + 1];
    float px = princpt[b * 2 + 0], py = princpt[b * 2 + 1];

    // (pixel - princpt) / focal : rn sub, rn div (XLA: separate ops, no FMA)
    float rx = __fdiv_rn(__fsub_rn(pc.x, px), fx);
    float ry = __fdiv_rn(__fsub_rn(pc.y, py), fy);
    float rz = 1.0f;

    const float* R = camrot + b * 9;   // camrot^T applied
    float dx = __fadd_rn(__fadd_rn(__fmul_rn(R[0], rx), __fmul_rn(R[3], ry)),
                         __fmul_rn(R[6], rz));
    float dy = __fadd_rn(__fadd_rn(__fmul_rn(R[1], rx), __fmul_rn(R[4], ry)),
                         __fmul_rn(R[7], rz));
    float dz = __fadd_rn(__fadd_rn(__fmul_rn(R[2], rx), __fmul_rn(R[5], ry)),
                         __fmul_rn(R[8], rz));

    float s = __fadd_rn(__fadd_rn(__fmul_rn(dx, dx), __fmul_rn(dy, dy)),
                        __fmul_rn(dz, dz));
    float nrm = sqrtf(s);
    dx = __fdiv_rn(dx, nrm);
    dy = __fdiv_rn(dy, nrm);
    dz = __fdiv_rn(dz, nrm);

    float cx = campos[b * 3 + 0], cy = campos[b * 3 + 1], cz = campos[b * 3 + 2];

    float t1x = __fdiv_rn(__fsub_rn(-1.0f, cx), dx);
    float t2x = __fdiv_rn(__fsub_rn( 1.0f, cx), dx);
    float t1y = __fdiv_rn(__fsub_rn(-1.0f, cy), dy);
    float t2y = __fdiv_rn(__fsub_rn( 1.0f, cy), dy);
    float t1z = __fdiv_rn(__fsub_rn(-1.0f, cz), dz);
    float t2z = __fdiv_rn(__fsub_rn( 1.0f, cz), dz);
    float tmin = fmaxf(fminf(t1x, t2x),
                 fmaxf(fminf(t1y, t2y), fminf(t1z, t2z)));
    float tmax = fminf(fmaxf(t1x, t2x),
                 fminf(fmaxf(t1y, t2y), fmaxf(t1z, t2z)));
    bool hit = tmin < tmax;
    float t0 = fmaxf(hit ? tmin : 0.0f, 0.0f);

    // pos = campos + raydir*t0 : separate rn mul + rn add (knife edge)
    float posx = __fadd_rn(cx, __fmul_rn(dx, t0));
    float posy = __fadd_rn(cy, __fmul_rn(dy, t0));
    float posz = __fadd_rn(cz, __fmul_rn(dz, t0));

    // DT = 2^-5 => dir*DT is exact; per-step pos update is one rn add.
    float sx = dx * DT, sy = dy * DT, sz = dz * DT;

    float accR = 0.0f, accG = 0.0f, accB = 0.0f, accA = 0.0f;

    if (hit) {
        const uint4* __restrict__ volb = g_vol + (size_t)b * VOXELS;
        bool wasValid = false;

        // ---- prologue: stage A = step 0 ----
        bool vA = (posx > -1.0f) & (posx < 1.0f) &
                  (posy > -1.0f) & (posy < 1.0f) &
                  (posz > -1.0f) & (posz < 1.0f);
        int xa, ya, za; float fxA, fyA, fzA;
        coord(posx, xa, fxA); coord(posy, ya, fyA); coord(posz, za, fzA);
        int bA = (((za << 7) + ya) << 7) + xa;
        uint4 A00 = __ldg(volb + bA);
        uint4 A01 = __ldg(volb + bA + DVOX);
        uint4 A10 = __ldg(volb + bA + DVOX * DVOX);
        uint4 A11 = __ldg(volb + bA + DVOX * DVOX + DVOX);

        // stage B position = step 1 (sequential rn chain, reference order)
        float pBx = posx + sx, pBy = posy + sy, pBz = posz + sz;

        // 56 iterations x 2 steps = 112; step 111 is the last real one and
        // step 112's prefetch is wasted-but-safe (clamped addresses). The
        // 112th *math* step is gated: position 111*DT=3.469 > 2*sqrt(3) is
        // provably outside the cube, so its valid flag is always false.
        #pragma unroll 1
        for (int it = 0; it < (NSTEPS + 1) / 2; ++it) {
            // ---- prepare stage B (valid, coords, prefetch loads) ----
            bool vB = (pBx > -1.0f) & (pBx < 1.0f) &
                      (pBy > -1.0f) & (pBy < 1.0f) &
                      (pBz > -1.0f) & (pBz < 1.0f);
            int xb, yb, zb; float fxB, fyB, fzB;
            coord(pBx, xb, fxB); coord(pBy, yb, fyB); coord(pBz, zb, fzB);
            int bB = (((zb << 7) + yb) << 7) + xb;
            uint4 B00 = __ldg(volb + bB);
            uint4 B01 = __ldg(volb + bB + DVOX);
            uint4 B10 = __ldg(volb + bB + DVOX * DVOX);
            uint4 B11 = __ldg(volb + bB + DVOX * DVOX + DVOX);

            // next-next position (step for the A-slot refill)
            float pCx = pBx + sx, pCy = pBy + sy, pCz = pBz + sz;

            // ---- math stage A ----
            {
                __half2 hfx = __float2half2_rn(fxA);
                __half2 hom = __float2half2_rn(1.0f - fxA);
                float4 c00 = xlerp(A00, hom, hfx);
                float4 c01 = xlerp(A01, hom, hfx);
                float4 c10 = xlerp(A10, hom, hfx);
                float4 c11 = xlerp(A11, hom, hfx);
                float4 c0  = lerp4(c00, c01, fyA);
                float4 c1  = lerp4(c10, c11, fyA);
                float4 smp = lerp4(c0, c1, fzA);
                float va = vA ? 1.0f : 0.0f;
                float contrib = (fminf(accA + smp.w * DT, 1.0f) - accA) * va;
                accR += smp.x * contrib;
                accG += smp.y * contrib;
                accB += smp.z * contrib;
                accA += contrib;
            }
            // volume >= 0: alpha saturates to exactly 1.0 -> contrib 0 forever
            if (accA >= 1.0f) break;
            // convex cube: once inside then outside, never inside again
            if (wasValid & !vA) break;
            wasValid |= vA;

            // ---- prepare stage A' (refill A buffers for step 2it+2) ----
            vA = (pCx > -1.0f) & (pCx < 1.0f) &
                 (pCy > -1.0f) & (pCy < 1.0f) &
                 (pCz > -1.0f) & (pCz < 1.0f);
            coord(pCx, xa, fxA); coord(pCy, ya, fyA); coord(pCz, za, fzA);
            bA = (((za << 7) + ya) << 7) + xa;
            A00 = __ldg(volb + bA);
            A01 = __ldg(volb + bA + DVOX);
            A10 = __ldg(volb + bA + DVOX * DVOX);
            A11 = __ldg(volb + bA + DVOX * DVOX + DVOX);

            // advance B position to step 2it+3 (sequential rn chain)
            pBx = pCx + sx; pBy = pCy + sy; pBz = pCz + sz;

            // ---- math stage B ----
            {
                __half2 hfx = __float2half2_rn(fxB);
                __half2 hom = __float2half2_rn(1.0f - fxB);
                float4 c00 = xlerp(B00, hom, hfx);
                float4 c01 = xlerp(B01, hom, hfx);
                float4 c10 = xlerp(B10, hom, hfx);
                float4 c11 = xlerp(B11, hom, hfx);
                float4 c0  = lerp4(c00, c01, fyB);
                float4 c1  = lerp4(c10, c11, fyB);
                float4 smp = lerp4(c0, c1, fzB);
                float vb = vB ? 1.0f : 0.0f;
                float contrib = (fminf(accA + smp.w * DT, 1.0f) - accA) * vb;
                accR += smp.x * contrib;
                accG += smp.y * contrib;
                accB += smp.z * contrib;
                accA += contrib;
            }
            if (accA >= 1.0f) break;
            if (wasValid & !vB) break;
            wasValid |= vB;
        }
    }

    // out: [B,4,H,W]
    int o = ((b * 4) * HPIX + h) * WPIX + w;
    const int CS = HPIX * WPIX;
    out[o]          = accR;
    out[o + CS]     = accG;
    out[o + 2 * CS] = accB;
    out[o + 3 * CS] = accA;
}

extern "C" void kernel_launch(void* const* d_in, const int* in_sizes, int n_in,
                              void* d_out, int out_size)
{
    const float* camrot      = (const float*)d_in[0];
    const float* campos      = (const float*)d_in[1];
    const float* focal       = (const float*)d_in[2];
    const float* princpt     = (const float*)d_in[3];
    const float* pixelcoords = (const float*)d_in[4];
    const float* volume      = (const float*)d_in[5];
    float* out = (float*)d_out;

    int B = in_sizes[1] / 3;                       // = 2
    int nrows = B * DVOX * DVOX;                   // one block per x-row
    interleave_kernel<<<nrows, DVOX>>>(volume);

    int npix = B * HPIX * WPIX;                    // 131072
    raymarch_kernel<<<npix / 128, 128>>>(camrot, campos, focal, princpt,
                                         pixelcoords, out);
}

// round 17
// speedup vs baseline: 1.3887x; 1.1564x over previous
#include <cuda_runtime.h>
#include <cuda_fp16.h>

// Problem constants (shapes fixed by setup_inputs): B=2, H=W=256, D=128, C=4.
constexpr int   DVOX    = 128;
constexpr int   HPIX    = 256;
constexpr int   WPIX    = 256;
constexpr int   BBATCH  = 2;
constexpr float DT      = 0.03125f;            // 2^-5, EXACT power of two
constexpr int   NSTEPS  = 111;                 // ceil(2*sqrt(3)/DT)
constexpr int   VOXELS  = DVOX * DVOX * DVOX;  // 2097152 per batch per channel

// 64 MB scratch: volume as fp16, x-pair duplicated:
// g_vol[b][z][y][x] = { c0..c3 @ x , c0..c3 @ x+1 }  (8 halves = 16 B, aligned)
// One LDG.128 fetches a full x-corner pair for all 4 channels.
__device__ uint4 g_vol[(size_t)BBATCH * VOXELS];

// ---------------------------------------------------------------------------
// Pass 1: fp16 convert + channel interleave + x-pair duplication.
// Moves 192 MB total -> already at HBM roofline (~23 us), compulsory traffic.
// ---------------------------------------------------------------------------
__global__ void __launch_bounds__(128)
interleave_kernel(const float* __restrict__ vol)
{
    __shared__ unsigned int s01[DVOX];   // half2(c0,c1) per x
    __shared__ unsigned int s23[DVOX];   // half2(c2,c3) per x

    int x   = threadIdx.x;
    int row = blockIdx.x;                        // flat over B * 128 * 128 rows
    int b   = row >> 14;                         // / (128*128)
    int zy  = row & (DVOX * DVOX - 1);

    const float* p = vol + (size_t)b * 4 * VOXELS + (size_t)zy * DVOX + x;
    __half2 a01 = __halves2half2(__float2half_rn(p[0]),
                                 __float2half_rn(p[VOXELS]));
    __half2 a23 = __halves2half2(__float2half_rn(p[2 * VOXELS]),
                                 __float2half_rn(p[3 * VOXELS]));
    s01[x] = *reinterpret_cast<unsigned int*>(&a01);
    s23[x] = *reinterpret_cast<unsigned int*>(&a23);
    __syncthreads();

    int x1 = (x < DVOX - 1) ? x + 1 : x;         // x=127 slot is never sampled
    uint4 u;
    u.x = s01[x];  u.y = s23[x];
    u.z = s01[x1]; u.w = s23[x1];
    g_vol[(size_t)b * VOXELS + (size_t)zy * DVOX + x] = u;
}

// ---------------------------------------------------------------------------
// sampling helpers (R6-measured-best math: half2 x-lerp, fp32 y/z lerps)
// ---------------------------------------------------------------------------
__device__ __forceinline__ __half2 H2(unsigned int u)
{
    return *reinterpret_cast<__half2*>(&u);
}

// x-lerp one (z,y) corner row in half2, then convert to fp32 float4.
__device__ __forceinline__ float4 xlerp(uint4 r, __half2 omfx, __half2 fx)
{
    __half2 c01 = __hfma2(H2(r.z), fx, __hmul2(H2(r.x), omfx));
    __half2 c23 = __hfma2(H2(r.w), fx, __hmul2(H2(r.y), omfx));
    float2 f01 = __half22float2(c01);
    float2 f23 = __half22float2(c23);
    return make_float4(f01.x, f01.y, f23.x, f23.y);
}

__device__ __forceinline__ float4 lerp4(float4 a, float4 b, float t)
{
    float omt = 1.0f - t;
    return make_float4(a.x * omt + b.x * t,
                       a.y * omt + b.y * t,
                       a.z * omt + b.z * t,
                       a.w * omt + b.w * t);
}

// Grid coord + cell index + frac. g = fma(pos, 63.5, 63.5) — continuous vs the
// reference's op chain (trilinear is continuous across cell flips); only the
// validity test (done on exact pos) is discrete. Integer clamp keeps the
// address in-bounds even for gated-off (invalid) positions.
__device__ __forceinline__ void coord(float pos, int& i0, float& fr)
{
    float g = __fmaf_rn(pos, 63.5f, 63.5f);
    int i = (int)g;                 // trunc == floor for g >= 0
    i0 = min(max(i, 0), 126);
    fr = g - (float)i0;
}

// Per-stage preparation: validity, fracs, and the 4 corner loads.
#define PREP_STAGE(PX, PY, PZ, V, FX, FY, FZ, B0, B1, B2, B3)                 \
    do {                                                                      \
        V = (PX > -1.0f) & (PX < 1.0f) &                                      \
            (PY > -1.0f) & (PY < 1.0f) &                                      \
            (PZ > -1.0f) & (PZ < 1.0f);                                       \
        int _x, _y, _z;                                                       \
        coord(PX, _x, FX); coord(PY, _y, FY); coord(PZ, _z, FZ);              \
        int _base = (((_z << 7) + _y) << 7) + _x;                             \
        B0 = __ldg(volb + _base);                                             \
        B1 = __ldg(volb + _base + DVOX);                                      \
        B2 = __ldg(volb + _base + DVOX * DVOX);                               \
        B3 = __ldg(volb + _base + DVOX * DVOX + DVOX);                        \
    } while (0)

// Math for one stage: trilinear sample + composite. Returns via accumulators.
#define MATH_STAGE(V, FX, FY, FZ, B0, B1, B2, B3)                             \
    do {                                                                      \
        __half2 _hfx = __float2half2_rn(FX);                                  \
        __half2 _hom = __float2half2_rn(1.0f - FX);                           \
        float4 _c00 = xlerp(B0, _hom, _hfx);                                  \
        float4 _c01 = xlerp(B1, _hom, _hfx);                                  \
        float4 _c10 = xlerp(B2, _hom, _hfx);                                  \
        float4 _c11 = xlerp(B3, _hom, _hfx);                                  \
        float4 _c0  = lerp4(_c00, _c01, FY);                                  \
        float4 _c1  = lerp4(_c10, _c11, FY);                                  \
        float4 _smp = lerp4(_c0, _c1, FZ);                                    \
        float _vf = V ? 1.0f : 0.0f;                                          \
        float _contrib = (fminf(accA + _smp.w * DT, 1.0f) - accA) * _vf;      \
        accR += _smp.x * _contrib;                                            \
        accG += _smp.y * _contrib;                                            \
        accB += _smp.z * _contrib;                                            \
        accA += _contrib;                                                     \
    } while (0)

// ---------------------------------------------------------------------------
// Pass 2: ray march, 3-stage software pipeline (A/B/C rotation): each load
// group has TWO stages of independent math (~180-200 cyc) between issue and
// first use — nearly covering the 234-cyc L2 hit latency that R15's ncu
// showed was the binder (one-stage distance covered only ~40% of it).
// Peak in-flight load regs unchanged (8 uint4); __launch_bounds__(128,7)
// holds regs <= 73 so all 7 blocks/SM stay resident (grid-limited occ).
// Warp = 32x1 pixel strip (measured-best locality). Ray setup replicates
// XLA's un-contracted fp32 chain bit-exactly (z=-1 face knife edge).
// ---------------------------------------------------------------------------
__global__ void __launch_bounds__(128, 7)
raymarch_kernel(const float* __restrict__ camrot,
                const float* __restrict__ campos,
                const float* __restrict__ focal,
                const float* __restrict__ princpt,
                const float* __restrict__ pixelcoords,
                float* __restrict__ out)
{
    int idx = blockIdx.x * blockDim.x + threadIdx.x;   // flat over B*H*W
    int w = idx & (WPIX - 1);
    int h = (idx >> 8) & (HPIX - 1);
    int b = idx >> 16;

    float2 pc = reinterpret_cast<const float2*>(pixelcoords)[idx];

    float fx = focal[b * 2 + 0], fy = focal[b * 2 + 1];
    float px = princpt[b * 2 + 0], py = princpt[b * 2 + 1];

    // (pixel - princpt) / focal : rn sub, rn div (XLA: separate ops, no FMA)
    float rx = __fdiv_rn(__fsub_rn(pc.x, px), fx);
    float ry = __fdiv_rn(__fsub_rn(pc.y, py), fy);
    float rz = 1.0f;

    const float* R = camrot + b * 9;   // camrot^T applied
    float dx = __fadd_rn(__fadd_rn(__fmul_rn(R[0], rx), __fmul_rn(R[3], ry)),
                         __fmul_rn(R[6], rz));
    float dy = __fadd_rn(__fadd_rn(__fmul_rn(R[1], rx), __fmul_rn(R[4], ry)),
                         __fmul_rn(R[7], rz));
    float dz = __fadd_rn(__fadd_rn(__fmul_rn(R[2], rx), __fmul_rn(R[5], ry)),
                         __fmul_rn(R[8], rz));

    float s = __fadd_rn(__fadd_rn(__fmul_rn(dx, dx), __fmul_rn(dy, dy)),
                        __fmul_rn(dz, dz));
    float nrm = sqrtf(s);
    dx = __fdiv_rn(dx, nrm);
    dy = __fdiv_rn(dy, nrm);
    dz = __fdiv_rn(dz, nrm);

    float cx = campos[b * 3 + 0], cy = campos[b * 3 + 1], cz = campos[b * 3 + 2];

    float t1x = __fdiv_rn(__fsub_rn(-1.0f, cx), dx);
    float t2x = __fdiv_rn(__fsub_rn( 1.0f, cx), dx);
    float t1y = __fdiv_rn(__fsub_rn(-1.0f, cy), dy);
    float t2y = __fdiv_rn(__fsub_rn( 1.0f, cy), dy);
    float t1z = __fdiv_rn(__fsub_rn(-1.0f, cz), dz);
    float t2z = __fdiv_rn(__fsub_rn( 1.0f, cz), dz);
    float tmin = fmaxf(fminf(t1x, t2x),
                 fmaxf(fminf(t1y, t2y), fminf(t1z, t2z)));
    float tmax = fminf(fmaxf(t1x, t2x),
                 fminf(fmaxf(t1y, t2y), fmaxf(t1z, t2z)));
    bool hit = tmin < tmax;
    float t0 = fmaxf(hit ? tmin : 0.0f, 0.0f);

    // pos = campos + raydir*t0 : separate rn mul + rn add (knife edge)
    float posx = __fadd_rn(cx, __fmul_rn(dx, t0));
    float posy = __fadd_rn(cy, __fmul_rn(dy, t0));
    float posz = __fadd_rn(cz, __fmul_rn(dz, t0));

    // DT = 2^-5 => dir*DT is exact; per-step pos update is one rn add.
    float sx = dx * DT, sy = dy * DT, sz = dz * DT;

    float accR = 0.0f, accG = 0.0f, accB = 0.0f, accA = 0.0f;

    if (hit) {
        const uint4* __restrict__ volb = g_vol + (size_t)b * VOXELS;
        bool wasValid = false;

        // Stage state
        bool vA, vB, vC;
        float fxA, fyA, fzA, fxB, fyB, fzB, fxC, fyC, fzC;
        uint4 A0, A1, A2, A3, B0, B1, B2, B3, C0, C1, C2, C3;

        // ---- prologue: A = step 0, B = step 1 ----
        PREP_STAGE(posx, posy, posz, vA, fxA, fyA, fzA, A0, A1, A2, A3);
        float p1x = posx + sx, p1y = posy + sy, p1z = posz + sz;   // step 1
        PREP_STAGE(p1x, p1y, p1z, vB, fxB, fyB, fzB, B0, B1, B2, B3);
        float p2x = p1x + sx, p2y = p1y + sy, p2z = p1z + sz;      // step 2

        // 38 triples = 114 steps; steps 111-113 are provably outside the cube
        // (111*DT = 3.46875 > 2*sqrt(3) = 3.4641), so their gated contribs
        // are exactly 0 and the extra prefetches read clamped in-bounds addrs.
        #pragma unroll 1
        for (int it = 0; it < (NSTEPS + 2) / 3; ++it) {
            // prep C (step 3it+2)
            PREP_STAGE(p2x, p2y, p2z, vC, fxC, fyC, fzC, C0, C1, C2, C3);
            float p3x = p2x + sx, p3y = p2y + sy, p3z = p2z + sz;

            // math A (step 3it)
            MATH_STAGE(vA, fxA, fyA, fzA, A0, A1, A2, A3);
            // volume >= 0: alpha saturates to exactly 1.0 -> contrib 0 forever
            if (accA >= 1.0f) break;
            // convex cube: once inside then outside, never inside again
            if (wasValid & !vA) break;
            wasValid |= vA;

            // refill A (step 3it+3)
            PREP_STAGE(p3x, p3y, p3z, vA, fxA, fyA, fzA, A0, A1, A2, A3);
            float p4x = p3x + sx, p4y = p3y + sy, p4z = p3z + sz;

            // math B (step 3it+1)
            MATH_STAGE(vB, fxB, fyB, fzB, B0, B1, B2, B3);
            if (accA >= 1.0f) break;
            if (wasValid & !vB) break;
            wasValid |= vB;

            // refill B (step 3it+4)
            PREP_STAGE(p4x, p4y, p4z, vB, fxB, fyB, fzB, B0, B1, B2, B3);
            p2x = p4x + sx; p2y = p4y + sy; p2z = p4z + sz;  // step 3it+5

            // math C (step 3it+2)
            MATH_STAGE(vC, fxC, fyC, fzC, C0, C1, C2, C3);
            if (accA >= 1.0f) break;
            if (wasValid & !vC) break;
            wasValid |= vC;
        }
    }

    // out: [B,4,H,W]
    int o = ((b * 4) * HPIX + h) * WPIX + w;
    const int CS = HPIX * WPIX;
    out[o]          = accR;
    out[o + CS]     = accG;
    out[o + 2 * CS] = accB;
    out[o + 3 * CS] = accA;
}

extern "C" void kernel_launch(void* const* d_in, const int* in_sizes, int n_in,
                              void* d_out, int out_size)
{
    const float* camrot      = (const float*)d_in[0];
    const float* campos      = (const float*)d_in[1];
    const float* focal       = (const float*)d_in[2];
    const float* princpt     = (const float*)d_in[3];
    const float* pixelcoords = (const float*)d_in[4];
    const float* volume      = (const float*)d_in[5];
    float* out = (float*)d_out;

    int B = in_sizes[1] / 3;                       // = 2
    int nrows = B * DVOX * DVOX;                   // one block per x-row
    interleave_kernel<<<nrows, DVOX>>>(volume);

    int npix = B * HPIX * WPIX;                    // 131072
    raymarch_kernel<<<npix / 128, 128>>>(camrot, campos, focal, princpt,
                                         pixelcoords, out);
}